// round 16
// baseline (speedup 1.0000x reference)
#include <cuda_runtime.h>

#define NN 131072          // N_NODES
#define NG 512             // NUM_GRAPHS
#define FIN 54
#define HG 16
#define TLEN 1024
#define NCLS 192
#define EMAX 4194304

typedef unsigned long long ull;

// ------------------------- scratch (no cudaMalloc allowed) -------------------
__device__ __align__(16) int   g_degi[NN];
__device__ __align__(16) float g_dinv[NN];
__device__ __align__(16) int   g_eoff[NN];
__device__ __align__(16) int   g_ecur[NN];
__device__ __align__(16) int   g_part[512];
__device__ __align__(16) int   g_psum[512];
__device__ __align__(16) int2  g_epk[EMAX];                         // {src, dinv[src]}
__device__ __align__(16) float g_xw[NN * HG];
__device__ __align__(16) float g_agg[NN * HG];
__device__ __align__(16) int   g_starts[NG];
__device__ __align__(16) float g_seq0[(size_t)NG * TLEN * HG];      // 33.5 MB
__device__ __align__(16) float g_h0[(size_t)NG * TLEN * 64];        // 134 MB
__device__ __align__(16) float g_pre[(size_t)2 * NG * TLEN * 128];  // 537 MB
__device__ __align__(16) float g_pooled[NG * 64];

// ------------------------- helpers ------------------------------------------
__device__ __forceinline__ ull pk2(float lo, float hi) {
    ull v; asm("mov.b64 %0, {%1, %2};" : "=l"(v) : "f"(lo), "f"(hi)); return v;
}
__device__ __forceinline__ void upk2(ull v, float& lo, float& hi) {
    asm("mov.b64 {%0, %1}, %2;" : "=f"(lo), "=f"(hi) : "l"(v));
}
#define FMA2(d, a, b) asm("fma.rn.f32x2 %0, %1, %2, %0;" : "+l"(d) : "l"(a), "l"(b))

__device__ __forceinline__ float tanh_fast(float x) {
    float y; asm("tanh.approx.f32 %0, %1;" : "=f"(y) : "f"(x)); return y;
}
__device__ __forceinline__ float sig_fast(float x) {
    return fmaf(0.5f, tanh_fast(0.5f * x), 0.5f);
}
__device__ __forceinline__ unsigned tf32c(float x) {
    unsigned u; asm("cvt.rna.tf32.f32 %0, %1;" : "=r"(u) : "f"(x)); return u;
}

// ------------------------- init + degree + scan + fill -----------------------
__global__ void init_kernel() {
    int idx = blockIdx.x * 256 + threadIdx.x;
    if (idx < (int)(NG * TLEN * HG / 4))
        ((float4*)g_seq0)[idx] = make_float4(0.f, 0.f, 0.f, 0.f);
    if (idx < NN) g_degi[idx] = 0;
}

__global__ void deg_kernel(const int* __restrict__ dst, int E) {
    int e = blockIdx.x * 256 + threadIdx.x;
    if (e < E) atomicAdd(&g_degi[dst[e]], 1);
}

__global__ void scan1_kernel() {
    __shared__ int sh[256];
    int tid = threadIdx.x;
    sh[tid] = g_degi[blockIdx.x * 256 + tid];
    __syncthreads();
    for (int o = 128; o > 0; o >>= 1) {
        if (tid < o) sh[tid] += sh[tid + o];
        __syncthreads();
    }
    if (tid == 0) g_part[blockIdx.x] = sh[0];
}

__global__ void scan2_kernel() {
    __shared__ int sh[512];
    int tid = threadIdx.x;
    sh[tid] = g_part[tid];
    __syncthreads();
    int v;
    for (int o = 1; o < 512; o <<= 1) {
        v = (tid >= o) ? sh[tid - o] : 0;
        __syncthreads();
        sh[tid] += v;
        __syncthreads();
    }
    g_psum[tid] = (tid == 0) ? 0 : sh[tid - 1];
}

__global__ void scan3_kernel() {
    __shared__ int sh[256];
    int tid = threadIdx.x;
    int n = blockIdx.x * 256 + tid;
    int d = g_degi[n];
    sh[tid] = d;
    __syncthreads();
    int v;
    for (int o = 1; o < 256; o <<= 1) {
        v = (tid >= o) ? sh[tid - o] : 0;
        __syncthreads();
        sh[tid] += v;
        __syncthreads();
    }
    int off = g_psum[blockIdx.x] + sh[tid] - d;   // exclusive
    g_eoff[n] = off;
    g_ecur[n] = off;
    g_dinv[n] = rsqrtf((float)(d + 1));           // +1 self-loop
}

__global__ void fill_kernel(const int* __restrict__ src, const int* __restrict__ dst, int E) {
    int e = blockIdx.x * 256 + threadIdx.x;
    if (e >= E) return;
    int s = src[e], d = dst[e];
    int pos = atomicAdd(&g_ecur[d], 1);
    g_epk[pos] = make_int2(s, __float_as_int(g_dinv[s]));
}

// ------------------------- GCN feature transform -----------------------------
__global__ __launch_bounds__(256) void xw1_kernel(const float* __restrict__ x,
                                                  const float* __restrict__ W) {
    __shared__ float Ws[FIN * HG];
    __shared__ float Xs[16 * FIN];
    int tid = threadIdx.x;
    for (int i = tid; i < FIN * HG; i += 256) Ws[i] = W[i];
    size_t base = (size_t)blockIdx.x * 16 * FIN;
    for (int i = tid; i < 16 * FIN; i += 256) Xs[i] = x[base + i];
    __syncthreads();
    int nl = tid >> 4, j = tid & 15;
    const float* xr = Xs + nl * FIN;
    float acc = 0.f;
#pragma unroll
    for (int d = 0; d < FIN; d++) acc = fmaf(xr[d], Ws[d * HG + j], acc);
    g_xw[(size_t)blockIdx.x * 256 + tid] = acc;
}

__global__ __launch_bounds__(256) void xw2_kernel(const float* __restrict__ W) {
    __shared__ float Ws[HG * HG];
    __shared__ float Xs[16 * HG];
    int tid = threadIdx.x;
    if (tid < HG * HG) Ws[tid] = W[tid];
    size_t base = (size_t)blockIdx.x * 16 * HG;
    if (tid < 64) ((float4*)Xs)[tid] = ((const float4*)(g_agg + base))[tid];
    __syncthreads();
    int nl = tid >> 4, j = tid & 15;
    const float* xr = Xs + nl * HG;
    float acc = 0.f;
#pragma unroll
    for (int d = 0; d < HG; d++) acc = fmaf(fmaxf(xr[d], 0.f), Ws[d * HG + j], acc);
    g_xw[(size_t)blockIdx.x * 256 + tid] = acc;
}

// ------------------------- gather-based conv (2 threads / node) --------------
// Measured 1.58x faster than 1-thread/node on identical work (R15 probe A/B).
__global__ __launch_bounds__(256) void conv_pair_kernel(const float* __restrict__ bias) {
    int idx = blockIdx.x * 256 + threadIdx.x;
    int n = idx >> 1, par = idx & 1;
    if (n >= NN) return;
    int e0 = g_eoff[n];
    int e1 = e0 + g_degi[n];
    float4 a0 = make_float4(0.f, 0.f, 0.f, 0.f), a1 = a0, a2 = a0, a3 = a0;
#pragma unroll 4
    for (int e = e0 + par; e < e1; e += 2) {
        int2 pk = g_epk[e];
        int s = pk.x;
        float nr = __int_as_float(pk.y);
        const float4* xs = (const float4*)(g_xw + (size_t)s * HG);
        float4 v0 = xs[0], v1 = xs[1], v2 = xs[2], v3 = xs[3];
        a0.x = fmaf(nr, v0.x, a0.x); a0.y = fmaf(nr, v0.y, a0.y);
        a0.z = fmaf(nr, v0.z, a0.z); a0.w = fmaf(nr, v0.w, a0.w);
        a1.x = fmaf(nr, v1.x, a1.x); a1.y = fmaf(nr, v1.y, a1.y);
        a1.z = fmaf(nr, v1.z, a1.z); a1.w = fmaf(nr, v1.w, a1.w);
        a2.x = fmaf(nr, v2.x, a2.x); a2.y = fmaf(nr, v2.y, a2.y);
        a2.z = fmaf(nr, v2.z, a2.z); a2.w = fmaf(nr, v2.w, a2.w);
        a3.x = fmaf(nr, v3.x, a3.x); a3.y = fmaf(nr, v3.y, a3.y);
        a3.z = fmaf(nr, v3.z, a3.z); a3.w = fmaf(nr, v3.w, a3.w);
    }
#define CMB(f) f += __shfl_xor_sync(0xffffffffu, f, 1)
    CMB(a0.x); CMB(a0.y); CMB(a0.z); CMB(a0.w);
    CMB(a1.x); CMB(a1.y); CMB(a1.z); CMB(a1.w);
    CMB(a2.x); CMB(a2.y); CMB(a2.z); CMB(a2.w);
    CMB(a3.x); CMB(a3.y); CMB(a3.z); CMB(a3.w);
#undef CMB
    if (par) return;
    float di = g_dinv[n];
    float d2 = di * di;
    const float4* xn = (const float4*)(g_xw + (size_t)n * HG);
    const float4* bb = (const float4*)bias;
    float4* out = (float4*)(g_agg + (size_t)n * HG);
    float4 q, b, w;
#define EMIT(acc, k) \
    w = xn[k]; b = bb[k]; \
    q.x = b.x + di * acc.x + d2 * w.x; q.y = b.y + di * acc.y + d2 * w.y; \
    q.z = b.z + di * acc.z + d2 * w.z; q.w = b.w + di * acc.w + d2 * w.w; \
    out[k] = q;
    EMIT(a0, 0) EMIT(a1, 1) EMIT(a2, 2) EMIT(a3, 3)
#undef EMIT
}

// ------------------------- ragged -> padded ---------------------------------
__global__ void starts_kernel(const int* __restrict__ batch) {
    int i = blockIdx.x * 256 + threadIdx.x;
    if (i >= NN) return;
    int b = batch[i];
    int bp = (i == 0) ? -1 : batch[i - 1];
    for (int g = bp + 1; g <= b; ++g) g_starts[g] = i;   // batch is sorted
}

__global__ void pack_kernel(const int* __restrict__ batch) {
    int idx = blockIdx.x * 256 + threadIdx.x;
    if (idx >= NN * 4) return;
    int n = idx >> 2, q = idx & 3;
    int g = batch[n];
    int pos = n - g_starts[g];
    if (pos >= TLEN) return;  // mode="drop"
    float4 v = ((const float4*)(g_agg + (size_t)n * HG))[q];
    v.x = fmaxf(v.x, 0.f); v.y = fmaxf(v.y, 0.f);
    v.z = fmaxf(v.z, 0.f); v.w = fmaxf(v.w, 0.f);
    ((float4*)(g_seq0 + ((size_t)g * TLEN + pos) * HG))[q] = v;
}

// ------------------------- LSTM input projection (batch GEMM, FMA2) ----------
template<int DIN>
__global__ __launch_bounds__(256) void gemm_pre_kernel(
    const float* __restrict__ X,      // [NG][TLEN][DIN]
    const float* __restrict__ wih,    // [2][128][DIN]
    const float* __restrict__ bih, const float* __restrict__ bhh) // [2][128]
{
    constexpr int WPAD = DIN + 4;
    constexpr int TT = 64;
    constexpr int TPG = 8;
    __shared__ float Ws[128 * WPAD];
    __shared__ float Bs[128];
    __shared__ float Xs[TT * DIN];

    int dir = blockIdx.z, row = blockIdx.y;
    int tb = blockIdx.x * TT;
    int tid = threadIdx.x;

    const float* Wg = wih + (size_t)dir * 128 * DIN;
    for (int i = tid; i < 128 * DIN; i += 256) {
        int r = i / DIN, k = i - r * DIN;
        Ws[r * WPAD + k] = Wg[i];
    }
    if (tid < 128) Bs[tid] = bih[dir * 128 + tid] + bhh[dir * 128 + tid];
    const float4* Xg = (const float4*)(X + ((size_t)row * TLEN + tb) * DIN);
    for (int i = tid; i < TT * DIN / 4; i += 256) ((float4*)Xs)[i] = Xg[i];
    __syncthreads();

    int j = tid & 31, grp = tid >> 5;
    const float* xb = Xs + grp * TPG * DIN;
    const float* w0 = Ws + (0 * 32 + j) * WPAD;
    const float* w1 = Ws + (1 * 32 + j) * WPAD;
    const float* w2 = Ws + (2 * 32 + j) * WPAD;
    const float* w3 = Ws + (3 * 32 + j) * WPAD;

    ull acc[TPG][4];
#pragma unroll
    for (int tt = 0; tt < TPG; tt++)
#pragma unroll
        for (int g = 0; g < 4; g++) acc[tt][g] = 0ull;

#pragma unroll
    for (int k = 0; k < DIN; k += 4) {
        ulonglong2 wv0 = *(const ulonglong2*)(w0 + k);
        ulonglong2 wv1 = *(const ulonglong2*)(w1 + k);
        ulonglong2 wv2 = *(const ulonglong2*)(w2 + k);
        ulonglong2 wv3 = *(const ulonglong2*)(w3 + k);
#pragma unroll
        for (int tt = 0; tt < TPG; tt++) {
            ulonglong2 xv = *(const ulonglong2*)(xb + tt * DIN + k);
            FMA2(acc[tt][0], xv.x, wv0.x); FMA2(acc[tt][0], xv.y, wv0.y);
            FMA2(acc[tt][1], xv.x, wv1.x); FMA2(acc[tt][1], xv.y, wv1.y);
            FMA2(acc[tt][2], xv.x, wv2.x); FMA2(acc[tt][2], xv.y, wv2.y);
            FMA2(acc[tt][3], xv.x, wv3.x); FMA2(acc[tt][3], xv.y, wv3.y);
        }
    }

    float b0 = Bs[j], b1 = Bs[32 + j], b2 = Bs[64 + j], b3 = Bs[96 + j];
    float4* Og = (float4*)(g_pre + (((size_t)dir * NG + row) * TLEN + tb + grp * TPG) * 128) + j;
#pragma unroll
    for (int tt = 0; tt < TPG; tt++) {
        float lo, hi; float4 o;
        upk2(acc[tt][0], lo, hi); o.x = lo + hi + b0;
        upk2(acc[tt][1], lo, hi); o.y = lo + hi + b1;
        upk2(acc[tt][2], lo, hi); o.z = lo + hi + b2;
        upk2(acc[tt][3], lo, hi); o.w = lo + hi + b3;
        Og[(size_t)tt * 32] = o;
    }
}

// ------------------------- tf32 MMA GEMM v2 (PROBE ONLY this round) ----------
// Fixes R11's defects: A fragments register-resident (loaded once), W staged
// in smem in exact fragment-register order packed 2 n-tiles per uint4, so the
// mainloop is 1x LDS.128 : 2x mma.m16n8k8 (R11 was 32 scalar LDS : 16 mma).
// Tile: 128 t-rows x 128 gate-cols per block, DIN=64. Same fragment math /
// epilogue as the numerically-verified R11 kernel.
__global__ __launch_bounds__(256) void gemm_mma2_kernel(
    const float* __restrict__ X,      // [NG][TLEN][64]
    const float* __restrict__ wih,    // [2][128][64]
    const float* __restrict__ bih, const float* __restrict__ bhh)
{
    constexpr int DIN = 64;
    constexpr int XS = DIN + 4;                   // 68
    extern __shared__ unsigned dsm[];
    unsigned* Xs = dsm;                           // [128][XS]
    uint4*    Bq = (uint4*)(dsm + 128 * XS);      // [8 kc][8 np][32 lane]
    float*    Bs = (float*)(dsm + 128 * XS + 8192); // [128] bias (p-order)

    int dir = blockIdx.z, row = blockIdx.y, tb = blockIdx.x * 128;
    int tid = threadIdx.x;

    // stage B fragments: Bq[kc][np][lane] = {b0(nt=2np), b1(2np), b0(2np+1), b1(2np+1)}
    // where b0 = W[p][8kc+m], b1 = W[p][8kc+m+4], p = nt*8+qr (perm p=j*4+g -> row g*32+j)
    for (int i = tid; i < 8 * 8 * 32; i += 256) {
        int lane = i & 31, rest = i >> 5;
        int np = rest & 7, kc = rest >> 3;
        int m = lane & 3, qr = lane >> 2;
        uint4 v;
#pragma unroll
        for (int h = 0; h < 2; h++) {
            int p = (np * 2 + h) * 8 + qr;
            int g = p & 3, j = p >> 2;
            const float* wr = wih + ((size_t)dir * 128 + g * 32 + j) * DIN;
            unsigned lo = tf32c(wr[8 * kc + m]);
            unsigned hi = tf32c(wr[8 * kc + m + 4]);
            if (h == 0) { v.x = lo; v.y = hi; } else { v.z = lo; v.w = hi; }
        }
        Bq[i] = v;
    }
    if (tid < 128) {
        int g = tid & 3, j = tid >> 2;
        Bs[tid] = bih[dir * 128 + g * 32 + j] + bhh[dir * 128 + g * 32 + j];
    }
    // stage X (tf32)
    {
        const float4* Xg = (const float4*)(X + ((size_t)row * TLEN + tb) * DIN);
        for (int i = tid; i < 128 * DIN / 4; i += 256) {
            float4 v = Xg[i];
            int r = i >> 4, k = (i & 15) * 4;
            unsigned* xp = Xs + r * XS + k;
            xp[0] = tf32c(v.x); xp[1] = tf32c(v.y);
            xp[2] = tf32c(v.z); xp[3] = tf32c(v.w);
        }
    }
    __syncthreads();

    int w = tid >> 5, lane = tid & 31;
    int qr = lane >> 2, m = lane & 3;

    // preload ALL A fragments (16 rows x 64 k per warp) into 32 regs
    unsigned a[8][4];
    {
        const unsigned* xr0 = Xs + (w * 16 + qr) * XS;
        const unsigned* xr1 = xr0 + 8 * XS;
#pragma unroll
        for (int kc = 0; kc < 8; kc++) {
            a[kc][0] = xr0[8 * kc + m];
            a[kc][1] = xr1[8 * kc + m];
            a[kc][2] = xr0[8 * kc + m + 4];
            a[kc][3] = xr1[8 * kc + m + 4];
        }
    }

    float c[16][4];
#pragma unroll
    for (int nt = 0; nt < 16; nt++) { c[nt][0] = c[nt][1] = c[nt][2] = c[nt][3] = 0.f; }

#pragma unroll
    for (int kc = 0; kc < 8; kc++) {
        const uint4* bp = Bq + kc * 8 * 32 + lane;
#pragma unroll
        for (int np = 0; np < 8; np++) {
            uint4 bq = bp[np * 32];
            asm volatile(
                "mma.sync.aligned.m16n8k8.row.col.f32.tf32.tf32.f32 "
                "{%0,%1,%2,%3}, {%4,%5,%6,%7}, {%8,%9}, {%0,%1,%2,%3};"
                : "+f"(c[2 * np][0]), "+f"(c[2 * np][1]), "+f"(c[2 * np][2]), "+f"(c[2 * np][3])
                : "r"(a[kc][0]), "r"(a[kc][1]), "r"(a[kc][2]), "r"(a[kc][3]),
                  "r"(bq.x), "r"(bq.y));
            asm volatile(
                "mma.sync.aligned.m16n8k8.row.col.f32.tf32.tf32.f32 "
                "{%0,%1,%2,%3}, {%4,%5,%6,%7}, {%8,%9}, {%0,%1,%2,%3};"
                : "+f"(c[2 * np + 1][0]), "+f"(c[2 * np + 1][1]), "+f"(c[2 * np + 1][2]), "+f"(c[2 * np + 1][3])
                : "r"(a[kc][0]), "r"(a[kc][1]), "r"(a[kc][2]), "r"(a[kc][3]),
                  "r"(bq.z), "r"(bq.w));
        }
    }

    // epilogue: + bias, interleaved layout (verified in R11)
    float* Og = g_pre + (((size_t)dir * NG + row) * TLEN + tb) * 128;
    int r0 = w * 16 + qr;
#pragma unroll
    for (int nt = 0; nt < 16; nt++) {
        int p0 = nt * 8 + m * 2;
        float2 bb = *(const float2*)(Bs + p0);
        *(float2*)(Og + (size_t)r0 * 128 + p0) = make_float2(c[nt][0] + bb.x, c[nt][1] + bb.y);
        *(float2*)(Og + (size_t)(r0 + 8) * 128 + p0) = make_float2(c[nt][2] + bb.x, c[nt][3] + bb.y);
    }
}

// ------------------------- LSTM recurrence -----------------------------------
// One warp per (row, dir); thread j owns hidden unit j. 4-deep register
// prefetch ring; dual accumulators per gate halve the FMA2 dependency chain.
template<bool IS_L0>
__global__ __launch_bounds__(32) void lstm_rec_kernel(const float* __restrict__ whh)
{
    int row = blockIdx.x, dir = blockIdx.y;
    int j = threadIdx.x;
    const float4* P = (const float4*)(g_pre + ((size_t)dir * NG + row) * TLEN * 128) + j;
    float* O = g_h0 + (size_t)row * TLEN * 64 + dir * 32 + j;

    ulonglong2 w[4][8];
#pragma unroll
    for (int g = 0; g < 4; g++) {
        const ulonglong2* wp = (const ulonglong2*)(whh + ((size_t)dir * 128 + g * 32 + j) * 32);
#pragma unroll
        for (int q = 0; q < 8; q++) w[g][q] = wp[q];
    }

    __shared__ __align__(16) float h_s[2][32];
    h_s[0][j] = 0.f;
    __syncwarp();

    int t0 = dir ? (TLEN - 1) : 0;
    int dt = dir ? -1 : 1;
    float c = 0.f, pool = 0.f;
    int buf = 0;

#define LOADP(s_) P[(size_t)(t0 + (s_) * dt) * 32]

#define STEP(pp, s_) { \
    ull a0 = pk2(pp.x, 0.f), a1 = pk2(pp.y, 0.f); \
    ull a2 = pk2(pp.z, 0.f), a3 = pk2(pp.w, 0.f); \
    ull b0 = 0ull, b1 = 0ull, b2 = 0ull, b3 = 0ull; \
    const ulonglong2* hv = (const ulonglong2*)h_s[buf]; \
    _Pragma("unroll") \
    for (int q = 0; q < 8; q++) { \
        ulonglong2 hh = hv[q]; \
        if (q < 4) { \
            FMA2(a0, hh.x, w[0][q].x); FMA2(a0, hh.y, w[0][q].y); \
            FMA2(a1, hh.x, w[1][q].x); FMA2(a1, hh.y, w[1][q].y); \
            FMA2(a2, hh.x, w[2][q].x); FMA2(a2, hh.y, w[2][q].y); \
            FMA2(a3, hh.x, w[3][q].x); FMA2(a3, hh.y, w[3][q].y); \
        } else { \
            FMA2(b0, hh.x, w[0][q].x); FMA2(b0, hh.y, w[0][q].y); \
            FMA2(b1, hh.x, w[1][q].x); FMA2(b1, hh.y, w[1][q].y); \
            FMA2(b2, hh.x, w[2][q].x); FMA2(b2, hh.y, w[2][q].y); \
            FMA2(b3, hh.x, w[3][q].x); FMA2(b3, hh.y, w[3][q].y); \
        } \
    } \
    float lo, hi, lo2, hi2; \
    upk2(a0, lo, hi); upk2(b0, lo2, hi2); float gi = sig_fast((lo + hi) + (lo2 + hi2)); \
    upk2(a1, lo, hi); upk2(b1, lo2, hi2); float gf = sig_fast((lo + hi) + (lo2 + hi2)); \
    upk2(a2, lo, hi); upk2(b2, lo2, hi2); float gg = tanh_fast((lo + hi) + (lo2 + hi2)); \
    upk2(a3, lo, hi); upk2(b3, lo2, hi2); float go = sig_fast((lo + hi) + (lo2 + hi2)); \
    c = gf * c + gi * gg; \
    float h = go * tanh_fast(c); \
    if (IS_L0) O[(size_t)(t0 + (s_) * dt) * 64] = h; \
    else       pool += h; \
    h_s[buf ^ 1][j] = h; \
    __syncwarp(); \
    buf ^= 1; }

    float4 p0 = LOADP(0);
    float4 p1 = LOADP(1);
    float4 p2 = LOADP(2);
    for (int s = 0; s < TLEN; s += 4) {
        float4 p3 = (s + 3 < TLEN) ? LOADP(s + 3) : p0;
        STEP(p0, s)
        float4 q0 = (s + 4 < TLEN) ? LOADP(s + 4) : p0;
        STEP(p1, s + 1)
        float4 q1 = (s + 5 < TLEN) ? LOADP(s + 5) : p0;
        STEP(p2, s + 2)
        float4 q2 = (s + 6 < TLEN) ? LOADP(s + 6) : p0;
        STEP(p3, s + 3)
        p0 = q0; p1 = q1; p2 = q2;
    }
#undef STEP
#undef LOADP
    if (!IS_L0) g_pooled[row * 64 + dir * 32 + j] = pool;
}

// ------------------------- FC + mean ----------------------------------------
__global__ void fc_kernel(const float* __restrict__ w, const float* __restrict__ b,
                          float* __restrict__ out) {
    int idx = blockIdx.x * 256 + threadIdx.x;
    if (idx >= NG * NCLS) return;
    int r = idx / NCLS, cc = idx - r * NCLS;
    const float* p = g_pooled + r * 64;
    float acc = 0.f;
#pragma unroll
    for (int k = 0; k < 64; k++) acc += p[k] * w[k * NCLS + cc];
    out[idx] = b[cc] + acc * (1.f / (float)TLEN);
}

// ------------------------- launch -------------------------------------------
extern "C" void kernel_launch(void* const* d_in, const int* in_sizes, int n_in,
                              void* d_out, int out_size) {
    const float* x     = (const float*)d_in[0];
    const int*   ei    = (const int*)d_in[1];
    const int*   batch = (const int*)d_in[2];
    const float* w1    = (const float*)d_in[3];
    const float* b1    = (const float*)d_in[4];
    const float* w2    = (const float*)d_in[5];
    const float* b2    = (const float*)d_in[6];
    const float* l0wih = (const float*)d_in[7];
    const float* l0whh = (const float*)d_in[8];
    const float* l0bih = (const float*)d_in[9];
    const float* l0bhh = (const float*)d_in[10];
    const float* l1wih = (const float*)d_in[11];
    const float* l1whh = (const float*)d_in[12];
    const float* l1bih = (const float*)d_in[13];
    const float* l1bhh = (const float*)d_in[14];
    const float* fcw   = (const float*)d_in[15];
    const float* fcb   = (const float*)d_in[16];
    float* out = (float*)d_out;

    int E = in_sizes[1] / 2;
    const int* src = ei;
    const int* dst = ei + E;

    float* seq0_p; cudaGetSymbolAddress((void**)&seq0_p, g_seq0);
    float* h0_p;   cudaGetSymbolAddress((void**)&h0_p, g_h0);

    const int SMM = (128 * 68 + 8192 + 128) * 4;   // 68096 B (Xs + Bq + Bs)
    cudaFuncSetAttribute(gemm_mma2_kernel, cudaFuncAttributeMaxDynamicSharedMemorySize, SMM);

    // CSR build
    init_kernel<<<8192, 256>>>();                          // launch 0
    deg_kernel<<<(E + 255) / 256, 256>>>(dst, E);          // launch 1
    scan1_kernel<<<512, 256>>>();                          // launch 2

    // PROBE (launch 3 = the one ncu profiles): 1/16-scale gemm_mma2 on
    // stale-but-deterministic g_h0. Same work quantum (65536 t-units) as the
    // R7 gemm_pre probe (41.6us) -> direct comparison. Its g_pre writes are
    // fully overwritten by the real gemm_pre<64> below; output unaffected.
    gemm_mma2_kernel<<<dim3(8, 64, 1), 256, SMM>>>(h0_p, l1wih, l1bih, l1bhh);

    scan2_kernel<<<1, 512>>>();                            // launch 4
    scan3_kernel<<<512, 256>>>();                          // launch 5
    fill_kernel<<<(E + 255) / 256, 256>>>(src, dst, E);

    // conv1 + conv2 (gather-based, 2 threads/node — measured 1.58x win)
    xw1_kernel<<<NN / 16, 256>>>(x, w1);
    conv_pair_kernel<<<NN * 2 / 256, 256>>>(b1);
    xw2_kernel<<<NN / 16, 256>>>(w2);
    conv_pair_kernel<<<NN * 2 / 256, 256>>>(b2);

    // pack
    starts_kernel<<<(NN + 255) / 256, 256>>>(batch);
    pack_kernel<<<(NN * 4 + 255) / 256, 256>>>(batch);

    // BiLSTM layer 0 (FMA2 tiled GEMM + 1-warp recurrence)
    gemm_pre_kernel<HG><<<dim3(TLEN / 64, NG, 2), 256>>>(seq0_p, l0wih, l0bih, l0bhh);
    lstm_rec_kernel<true><<<dim3(NG, 2), 32>>>(l0whh);

    // BiLSTM layer 1 (fuses mean pooling)
    gemm_pre_kernel<64><<<dim3(TLEN / 64, NG, 2), 256>>>(h0_p, l1wih, l1bih, l1bhh);
    lstm_rec_kernel<false><<<dim3(NG, 2), 32>>>(l1whh);

    fc_kernel<<<(NG * NCLS + 255) / 256, 256>>>(fcw, fcb, out);
}